// round 1
// baseline (speedup 1.0000x reference)
#include <cuda_runtime.h>
#include <cstdint>

// Problem constants (fixed by the dataset)
#define BATCH 32
#define NQ    512
#define HD    1024
#define OD    1024

// Tiling
#define BM 128
#define BN 128
#define BK 16
#define KTILES (HD / BK)   // 64
#define LDA 20             // smem row stride in floats (conflict-free frag loads)
#define THREADS 256

__device__ __forceinline__ uint32_t cvta_smem(const void* p) {
    return (uint32_t)__cvta_generic_to_shared(p);
}

__device__ __forceinline__ void cp_async16(uint32_t smem, const void* gmem) {
    asm volatile("cp.async.cg.shared.global [%0], [%1], 16;\n" :: "r"(smem), "l"(gmem));
}

__device__ __forceinline__ uint32_t f2tf32(float f) {
    uint32_t r;
    asm("cvt.rna.tf32.f32 %0, %1;\n" : "=r"(r) : "f"(f));
    return r;
}

__global__ __launch_bounds__(THREADS, 2)
void scl_tf32_kernel(const float* __restrict__ x,
                     const int*   __restrict__ sid,
                     const float* __restrict__ weight,
                     const float* __restrict__ bias,
                     float*       __restrict__ y) {
    __shared__ float As[2][BM * LDA];
    __shared__ float Bs[2][BN * LDA];

    const int b  = blockIdx.z;
    const int s  = __ldg(&sid[b]);
    const int m0 = blockIdx.y * BM;   // N (query) tile
    const int n0 = blockIdx.x * BN;   // O tile

    const float* xb = x      + (size_t)b * NQ * HD + (size_t)m0 * HD;
    const float* wb = weight + (size_t)s * OD * HD + (size_t)n0 * HD;

    const int tid  = threadIdx.x;
    const int lrow = tid >> 2;          // 0..63 : loader row base
    const int lq   = (tid & 3) * 4;     // 0,4,8,12 : loader col (floats)

    const int wid  = tid >> 5;
    const int lane = tid & 31;
    const int g    = lane >> 2;         // groupID 0..7
    const int tg   = lane & 3;          // threadInGroup 0..3
    const int wm   = (wid & 1) * 64;    // warp M offset
    const int wn   = (wid >> 1) * 32;   // warp N offset

    float acc[4][4][4];
    #pragma unroll
    for (int i = 0; i < 4; i++)
        #pragma unroll
        for (int j = 0; j < 4; j++)
            #pragma unroll
            for (int k = 0; k < 4; k++) acc[i][j][k] = 0.f;

    auto load_stage = [&](int st, int k0) {
        #pragma unroll
        for (int i = 0; i < 2; i++) {
            const int row = lrow + i * 64;
            cp_async16(cvta_smem(&As[st][row * LDA + lq]),
                       xb + (size_t)row * HD + k0 + lq);
            cp_async16(cvta_smem(&Bs[st][row * LDA + lq]),
                       wb + (size_t)row * HD + k0 + lq);
        }
        asm volatile("cp.async.commit_group;\n" ::: "memory");
    };

    load_stage(0, 0);

    for (int kt = 0; kt < KTILES; kt++) {
        asm volatile("cp.async.wait_group 0;\n" ::: "memory");
        __syncthreads();

        const int cur = kt & 1;
        if (kt + 1 < KTILES) load_stage(cur ^ 1, (kt + 1) * BK);

        const float* A   = As[cur];
        const float* Bsm = Bs[cur];

        #pragma unroll
        for (int ks = 0; ks < 2; ks++) {
            const int kl = ks * 8;
            uint32_t af[4][4], bf[4][2];

            #pragma unroll
            for (int mi = 0; mi < 4; mi++) {
                const int r0 = wm + mi * 16 + g;
                af[mi][0] = f2tf32(A[ r0      * LDA + kl + tg    ]);
                af[mi][1] = f2tf32(A[(r0 + 8) * LDA + kl + tg    ]);
                af[mi][2] = f2tf32(A[ r0      * LDA + kl + tg + 4]);
                af[mi][3] = f2tf32(A[(r0 + 8) * LDA + kl + tg + 4]);
            }
            #pragma unroll
            for (int ni = 0; ni < 4; ni++) {
                const int c0 = wn + ni * 8 + g;
                bf[ni][0] = f2tf32(Bsm[c0 * LDA + kl + tg    ]);
                bf[ni][1] = f2tf32(Bsm[c0 * LDA + kl + tg + 4]);
            }

            #pragma unroll
            for (int mi = 0; mi < 4; mi++)
                #pragma unroll
                for (int ni = 0; ni < 4; ni++) {
                    asm volatile(
                        "mma.sync.aligned.m16n8k8.row.col.f32.tf32.tf32.f32 "
                        "{%0,%1,%2,%3}, {%4,%5,%6,%7}, {%8,%9}, {%0,%1,%2,%3};\n"
                        : "+f"(acc[mi][ni][0]), "+f"(acc[mi][ni][1]),
                          "+f"(acc[mi][ni][2]), "+f"(acc[mi][ni][3])
                        : "r"(af[mi][0]), "r"(af[mi][1]),
                          "r"(af[mi][2]), "r"(af[mi][3]),
                          "r"(bf[ni][0]), "r"(bf[ni][1]));
                }
        }
        __syncthreads();
    }

    // Epilogue: bias add + store
    const float* bb = bias + (size_t)s * OD + n0;
    float* yb = y + (size_t)b * NQ * OD + (size_t)m0 * OD + n0;

    #pragma unroll
    for (int mi = 0; mi < 4; mi++) {
        const int row = wm + mi * 16 + g;
        #pragma unroll
        for (int ni = 0; ni < 4; ni++) {
            const int col = wn + ni * 8 + tg * 2;
            const float b0v = __ldg(&bb[col]);
            const float b1v = __ldg(&bb[col + 1]);
            float2 v0 = make_float2(acc[mi][ni][0] + b0v, acc[mi][ni][1] + b1v);
            float2 v1 = make_float2(acc[mi][ni][2] + b0v, acc[mi][ni][3] + b1v);
            *reinterpret_cast<float2*>(&yb[(size_t)row * OD + col])       = v0;
            *reinterpret_cast<float2*>(&yb[(size_t)(row + 8) * OD + col]) = v1;
        }
    }
}

extern "C" void kernel_launch(void* const* d_in, const int* in_sizes, int n_in,
                              void* d_out, int out_size) {
    const float* x    = (const float*)d_in[0];
    const int*   sid  = (const int*)  d_in[1];
    const float* w    = (const float*)d_in[2];
    const float* bias = (const float*)d_in[3];
    float* y = (float*)d_out;

    dim3 grid(OD / BN, NQ / BM, BATCH);  // (8, 4, 32)
    scl_tf32_kernel<<<grid, THREADS>>>(x, sid, w, bias, y);
}

// round 4
// speedup vs baseline: 1.0795x; 1.0795x over previous
#include <cuda_runtime.h>
#include <cstdint>

// Problem constants
#define BATCH 32
#define NQ    512
#define HD    1024
#define OD    1024
#define NSUBJ 8

// Tiling
#define BM 128
#define BN 128
#define BK 16
#define KTILES (HD / BK)     // 64
#define LDA 20               // smem row stride in floats (conflict-free frag loads)
#define STAGES 4
#define ATILE (BM * LDA)     // floats per stage (A and B each)
#define THREADS 256
#define SMEM_BYTES (STAGES * 2 * ATILE * 4)   // 81920

// Scratch: weight pre-rounded to nearest-tf32 (MMA truncates raw fp32 operands)
__device__ float g_w_tf32[(size_t)NSUBJ * OD * HD];

__device__ __forceinline__ uint32_t cvta_smem(const void* p) {
    return (uint32_t)__cvta_generic_to_shared(p);
}

__device__ __forceinline__ void cp_async16(uint32_t smem, const void* gmem) {
    asm volatile("cp.async.cg.shared.global [%0], [%1], 16;\n" :: "r"(smem), "l"(gmem));
}

// ---------------- prologue: round W to nearest-tf32 ----------------
__global__ void __launch_bounds__(256) round_w_kernel(const float* __restrict__ w) {
    const size_t n = (size_t)NSUBJ * OD * HD;
    size_t i = ((size_t)blockIdx.x * blockDim.x + threadIdx.x) * 4;
    const size_t stride = (size_t)gridDim.x * blockDim.x * 4;
    for (; i < n; i += stride) {
        float4 v = *reinterpret_cast<const float4*>(w + i);
        uint32_t a, b, c, d;
        asm("cvt.rna.tf32.f32 %0, %1;" : "=r"(a) : "f"(v.x));
        asm("cvt.rna.tf32.f32 %0, %1;" : "=r"(b) : "f"(v.y));
        asm("cvt.rna.tf32.f32 %0, %1;" : "=r"(c) : "f"(v.z));
        asm("cvt.rna.tf32.f32 %0, %1;" : "=r"(d) : "f"(v.w));
        float4 o = make_float4(__uint_as_float(a), __uint_as_float(b),
                               __uint_as_float(c), __uint_as_float(d));
        *reinterpret_cast<float4*>(g_w_tf32 + i) = o;
    }
}

// ---------------- main GEMM ----------------
__global__ __launch_bounds__(THREADS, 2)
void scl_tf32_v2(const float* __restrict__ x,
                 const int*   __restrict__ sid,
                 const float* __restrict__ bias,
                 float*       __restrict__ y) {
    extern __shared__ float smf[];
    float* As = smf;                    // [STAGES][ATILE]
    float* Bs = smf + STAGES * ATILE;   // [STAGES][ATILE]

    const int b  = blockIdx.z;
    const int s  = __ldg(&sid[b]);
    const int m0 = blockIdx.y * BM;     // N (query) tile
    const int n0 = blockIdx.x * BN;     // O tile

    const float* xb = x        + (size_t)b * NQ * HD + (size_t)m0 * HD;
    const float* wb = g_w_tf32 + (size_t)s * OD * HD + (size_t)n0 * HD;

    const int tid  = threadIdx.x;
    const int lrow = tid >> 2;          // 0..63 loader row base
    const int lq   = (tid & 3) * 4;     // 0,4,8,12 loader col

    const int wid  = tid >> 5;
    const int lane = tid & 31;
    const int g    = lane >> 2;         // groupID 0..7
    const int tg   = lane & 3;          // threadInGroup 0..3
    const int wm   = (wid & 1) * 64;    // warp M offset
    const int wn   = (wid >> 1) * 32;   // warp N offset

    float acc[4][4][4];
    #pragma unroll
    for (int i = 0; i < 4; i++)
        #pragma unroll
        for (int j = 0; j < 4; j++)
            #pragma unroll
            for (int k = 0; k < 4; k++) acc[i][j][k] = 0.f;

    auto load_stage = [&](int st, int k0) {
        float* Ad = As + st * ATILE;
        float* Bd = Bs + st * ATILE;
        #pragma unroll
        for (int i = 0; i < 2; i++) {
            const int row = lrow + i * 64;
            cp_async16(cvta_smem(Ad + row * LDA + lq), xb + (size_t)row * HD + k0 + lq);
            cp_async16(cvta_smem(Bd + row * LDA + lq), wb + (size_t)row * HD + k0 + lq);
        }
    };

    // Prologue: fill STAGES-1 stages
    #pragma unroll
    for (int p = 0; p < STAGES - 1; p++) {
        load_stage(p, p * BK);
        asm volatile("cp.async.commit_group;\n" ::: "memory");
    }

    for (int kt = 0; kt < KTILES; kt++) {
        asm volatile("cp.async.wait_group %0;\n" :: "n"(STAGES - 2) : "memory");
        __syncthreads();

        // Issue the next stage (or an empty group to keep the count moving)
        const int nx = kt + STAGES - 1;
        if (nx < KTILES) load_stage(nx & (STAGES - 1), nx * BK);
        asm volatile("cp.async.commit_group;\n" ::: "memory");

        const float* A   = As + (kt & (STAGES - 1)) * ATILE;
        const float* Bsm = Bs + (kt & (STAGES - 1)) * ATILE;

        #pragma unroll
        for (int ks = 0; ks < 2; ks++) {
            const int kl = ks * 8;
            uint32_t af[4][4], bf[4][2];

            #pragma unroll
            for (int mi = 0; mi < 4; mi++) {
                const int r0 = wm + mi * 16 + g;
                af[mi][0] = __float_as_uint(A[ r0      * LDA + kl + tg    ]);
                af[mi][1] = __float_as_uint(A[(r0 + 8) * LDA + kl + tg    ]);
                af[mi][2] = __float_as_uint(A[ r0      * LDA + kl + tg + 4]);
                af[mi][3] = __float_as_uint(A[(r0 + 8) * LDA + kl + tg + 4]);
            }
            #pragma unroll
            for (int ni = 0; ni < 4; ni++) {
                const int c0 = wn + ni * 8 + g;
                bf[ni][0] = __float_as_uint(Bsm[c0 * LDA + kl + tg    ]);
                bf[ni][1] = __float_as_uint(Bsm[c0 * LDA + kl + tg + 4]);
            }

            #pragma unroll
            for (int mi = 0; mi < 4; mi++)
                #pragma unroll
                for (int ni = 0; ni < 4; ni++) {
                    asm volatile(
                        "mma.sync.aligned.m16n8k8.row.col.f32.tf32.tf32.f32 "
                        "{%0,%1,%2,%3}, {%4,%5,%6,%7}, {%8,%9}, {%0,%1,%2,%3};\n"
                        : "+f"(acc[mi][ni][0]), "+f"(acc[mi][ni][1]),
                          "+f"(acc[mi][ni][2]), "+f"(acc[mi][ni][3])
                        : "r"(af[mi][0]), "r"(af[mi][1]),
                          "r"(af[mi][2]), "r"(af[mi][3]),
                          "r"(bf[ni][0]), "r"(bf[ni][1]));
                }
        }
    }

    // Epilogue: bias add + store
    const float* bb = bias + (size_t)s * OD + n0;
    float* yb = y + (size_t)b * NQ * OD + (size_t)m0 * OD + n0;

    #pragma unroll
    for (int mi = 0; mi < 4; mi++) {
        const int row = wm + mi * 16 + g;
        #pragma unroll
        for (int ni = 0; ni < 4; ni++) {
            const int col = wn + ni * 8 + tg * 2;
            const float b0v = __ldg(&bb[col]);
            const float b1v = __ldg(&bb[col + 1]);
            float2 v0 = make_float2(acc[mi][ni][0] + b0v, acc[mi][ni][1] + b1v);
            float2 v1 = make_float2(acc[mi][ni][2] + b0v, acc[mi][ni][3] + b1v);
            *reinterpret_cast<float2*>(&yb[(size_t)row * OD + col])       = v0;
            *reinterpret_cast<float2*>(&yb[(size_t)(row + 8) * OD + col]) = v1;
        }
    }
}

extern "C" void kernel_launch(void* const* d_in, const int* in_sizes, int n_in,
                              void* d_out, int out_size) {
    const float* x    = (const float*)d_in[0];
    const int*   sid  = (const int*)  d_in[1];
    const float* w    = (const float*)d_in[2];
    const float* bias = (const float*)d_in[3];
    float* y = (float*)d_out;

    round_w_kernel<<<512, 256>>>(w);

    cudaFuncSetAttribute(scl_tf32_v2, cudaFuncAttributeMaxDynamicSharedMemorySize, SMEM_BYTES);

    dim3 grid(OD / BN, NQ / BM, BATCH);  // (8, 4, 32)
    scl_tf32_v2<<<grid, THREADS, SMEM_BYTES>>>(x, sid, bias, y);
}

// round 5
// speedup vs baseline: 1.1186x; 1.0362x over previous
#include <cuda_runtime.h>
#include <cstdint>

// Problem constants
#define BATCH 32
#define NQ    512
#define HD    1024
#define OD    1024
#define NSUBJ 8

// Tiling: CTA 128x128, 4 warps each computing a 64x64 tile
#define BM 128
#define BN 128
#define BK 16
#define KTILES (HD / BK)     // 64
#define LDA 20               // smem row stride in floats (conflict-free frag loads)
#define STAGES 4
#define ATILE (BM * LDA)     // floats per stage per operand
#define THREADS 128
#define SMEM_BYTES (STAGES * 2 * ATILE * 4)   // 81920

// Scratch: weight pre-rounded to nearest-tf32 (MMA truncates raw fp32 operands)
__device__ float g_w_tf32[(size_t)NSUBJ * OD * HD];

__device__ __forceinline__ uint32_t cvta_smem(const void* p) {
    return (uint32_t)__cvta_generic_to_shared(p);
}

__device__ __forceinline__ void cp_async16(uint32_t smem, const void* gmem) {
    asm volatile("cp.async.cg.shared.global [%0], [%1], 16;\n" :: "r"(smem), "l"(gmem));
}

// ---------------- prologue: round W to nearest-tf32 ----------------
__global__ void __launch_bounds__(256) round_w_kernel(const float* __restrict__ w) {
    const size_t n = (size_t)NSUBJ * OD * HD;
    size_t i = ((size_t)blockIdx.x * blockDim.x + threadIdx.x) * 4;
    const size_t stride = (size_t)gridDim.x * blockDim.x * 4;
    for (; i < n; i += stride) {
        float4 v = *reinterpret_cast<const float4*>(w + i);
        uint32_t a, b, c, d;
        asm("cvt.rna.tf32.f32 %0, %1;" : "=r"(a) : "f"(v.x));
        asm("cvt.rna.tf32.f32 %0, %1;" : "=r"(b) : "f"(v.y));
        asm("cvt.rna.tf32.f32 %0, %1;" : "=r"(c) : "f"(v.z));
        asm("cvt.rna.tf32.f32 %0, %1;" : "=r"(d) : "f"(v.w));
        float4 o = make_float4(__uint_as_float(a), __uint_as_float(b),
                               __uint_as_float(c), __uint_as_float(d));
        *reinterpret_cast<float4*>(g_w_tf32 + i) = o;
    }
}

// ---------------- main GEMM ----------------
__global__ __launch_bounds__(THREADS, 2)
void scl_tf32_v3(const float* __restrict__ x,
                 const int*   __restrict__ sid,
                 const float* __restrict__ bias,
                 float*       __restrict__ y) {
    extern __shared__ float smf[];
    float* As = smf;                    // [STAGES][ATILE]
    float* Bs = smf + STAGES * ATILE;   // [STAGES][ATILE]

    const int b  = blockIdx.z;
    const int s  = __ldg(&sid[b]);
    const int m0 = blockIdx.y * BM;     // N (query) tile
    const int n0 = blockIdx.x * BN;     // O tile

    const float* xb = x        + (size_t)b * NQ * HD + (size_t)m0 * HD;
    const float* wb = g_w_tf32 + (size_t)s * OD * HD + (size_t)n0 * HD;

    const int tid  = threadIdx.x;
    const int lrow = tid >> 2;          // 0..31 loader row base
    const int lq   = (tid & 3) * 4;     // 0,4,8,12 loader col

    const int wid  = tid >> 5;          // 0..3
    const int lane = tid & 31;
    const int g    = lane >> 2;         // groupID 0..7
    const int tg   = lane & 3;          // threadInGroup 0..3
    const int wm   = (wid & 1) * 64;    // warp M offset
    const int wn   = (wid >> 1) * 64;   // warp N offset

    float acc[4][8][4];
    #pragma unroll
    for (int i = 0; i < 4; i++)
        #pragma unroll
        for (int j = 0; j < 8; j++)
            #pragma unroll
            for (int k = 0; k < 4; k++) acc[i][j][k] = 0.f;

    auto load_stage = [&](int st, int k0) {
        float* Ad = As + st * ATILE;
        float* Bd = Bs + st * ATILE;
        #pragma unroll
        for (int i = 0; i < 4; i++) {
            const int row = lrow + i * 32;
            cp_async16(cvta_smem(Ad + row * LDA + lq), xb + (size_t)row * HD + k0 + lq);
            cp_async16(cvta_smem(Bd + row * LDA + lq), wb + (size_t)row * HD + k0 + lq);
        }
    };

    // Prologue: fill STAGES-1 stages
    #pragma unroll
    for (int p = 0; p < STAGES - 1; p++) {
        load_stage(p, p * BK);
        asm volatile("cp.async.commit_group;\n" ::: "memory");
    }

    for (int kt = 0; kt < KTILES; kt++) {
        asm volatile("cp.async.wait_group %0;\n" :: "n"(STAGES - 2) : "memory");
        __syncthreads();

        const int nx = kt + STAGES - 1;
        if (nx < KTILES) load_stage(nx & (STAGES - 1), nx * BK);
        asm volatile("cp.async.commit_group;\n" ::: "memory");

        const float* A   = As + (kt & (STAGES - 1)) * ATILE;
        const float* Bsm = Bs + (kt & (STAGES - 1)) * ATILE;

        #pragma unroll
        for (int ks = 0; ks < 2; ks++) {
            const int kl = ks * 8;
            uint32_t af[4][4], bf[8][2];

            #pragma unroll
            for (int mi = 0; mi < 4; mi++) {
                const int r0 = wm + mi * 16 + g;
                af[mi][0] = __float_as_uint(A[ r0      * LDA + kl + tg    ]);
                af[mi][1] = __float_as_uint(A[(r0 + 8) * LDA + kl + tg    ]);
                af[mi][2] = __float_as_uint(A[ r0      * LDA + kl + tg + 4]);
                af[mi][3] = __float_as_uint(A[(r0 + 8) * LDA + kl + tg + 4]);
            }
            #pragma unroll
            for (int ni = 0; ni < 8; ni++) {
                const int c0 = wn + ni * 8 + g;
                bf[ni][0] = __float_as_uint(Bsm[c0 * LDA + kl + tg    ]);
                bf[ni][1] = __float_as_uint(Bsm[c0 * LDA + kl + tg + 4]);
            }

            #pragma unroll
            for (int mi = 0; mi < 4; mi++)
                #pragma unroll
                for (int ni = 0; ni < 8; ni++) {
                    asm volatile(
                        "mma.sync.aligned.m16n8k8.row.col.f32.tf32.tf32.f32 "
                        "{%0,%1,%2,%3}, {%4,%5,%6,%7}, {%8,%9}, {%0,%1,%2,%3};\n"
                        : "+f"(acc[mi][ni][0]), "+f"(acc[mi][ni][1]),
                          "+f"(acc[mi][ni][2]), "+f"(acc[mi][ni][3])
                        : "r"(af[mi][0]), "r"(af[mi][1]),
                          "r"(af[mi][2]), "r"(af[mi][3]),
                          "r"(bf[ni][0]), "r"(bf[ni][1]));
                }
        }
    }

    // Epilogue: bias add + store
    const float* bb = bias + (size_t)s * OD + n0;
    float* yb = y + (size_t)b * NQ * OD + (size_t)m0 * OD + n0;

    #pragma unroll
    for (int mi = 0; mi < 4; mi++) {
        const int row = wm + mi * 16 + g;
        #pragma unroll
        for (int ni = 0; ni < 8; ni++) {
            const int col = wn + ni * 8 + tg * 2;
            const float b0v = __ldg(&bb[col]);
            const float b1v = __ldg(&bb[col + 1]);
            float2 v0 = make_float2(acc[mi][ni][0] + b0v, acc[mi][ni][1] + b1v);
            float2 v1 = make_float2(acc[mi][ni][2] + b0v, acc[mi][ni][3] + b1v);
            *reinterpret_cast<float2*>(&yb[(size_t)row * OD + col])       = v0;
            *reinterpret_cast<float2*>(&yb[(size_t)(row + 8) * OD + col]) = v1;
        }
    }
}

extern "C" void kernel_launch(void* const* d_in, const int* in_sizes, int n_in,
                              void* d_out, int out_size) {
    const float* x    = (const float*)d_in[0];
    const int*   sid  = (const int*)  d_in[1];
    const float* w    = (const float*)d_in[2];
    const float* bias = (const float*)d_in[3];
    float* y = (float*)d_out;

    round_w_kernel<<<512, 256>>>(w);

    cudaFuncSetAttribute(scl_tf32_v3, cudaFuncAttributeMaxDynamicSharedMemorySize, SMEM_BYTES);

    dim3 grid(OD / BN, NQ / BM, BATCH);  // (8, 4, 32)
    scl_tf32_v3<<<grid, THREADS, SMEM_BYTES>>>(x, sid, bias, y);
}

// round 6
// speedup vs baseline: 1.3177x; 1.1780x over previous
#include <cuda_runtime.h>
#include <cstdint>

// Problem constants
#define BATCH 32
#define NQ    512
#define HD    1024
#define OD    1024
#define NSUBJ 8

// Tiling: CTA 128x128, 4 warps each computing a 64x64 tile
#define BM 128
#define BN 128
#define BK 16
#define KTILES (HD / BK)     // 64
#define LDA 20               // smem row stride in floats (conflict-free frag loads)
#define STAGES 4
#define ATILE (BM * LDA)     // floats per stage per operand
#define THREADS 128
#define SMEM_BYTES (STAGES * 2 * ATILE * 4)   // 81920

// Scratch: weight pre-rounded to nearest-tf32 (MMA truncates raw fp32 operands)
__device__ float g_w_tf32[(size_t)NSUBJ * OD * HD];

__device__ __forceinline__ uint32_t cvta_smem(const void* p) {
    return (uint32_t)__cvta_generic_to_shared(p);
}

__device__ __forceinline__ void cp_async16(uint32_t smem, const void* gmem) {
    asm volatile("cp.async.cg.shared.global [%0], [%1], 16;\n" :: "r"(smem), "l"(gmem));
}

// ---------------- prologue: round W to nearest-tf32 ----------------
__global__ void __launch_bounds__(256) round_w_kernel(const float* __restrict__ w) {
    const size_t n = (size_t)NSUBJ * OD * HD;
    size_t i = ((size_t)blockIdx.x * blockDim.x + threadIdx.x) * 4;
    const size_t stride = (size_t)gridDim.x * blockDim.x * 4;
    for (; i < n; i += stride) {
        float4 v = *reinterpret_cast<const float4*>(w + i);
        uint32_t a, b, c, d;
        asm("cvt.rna.tf32.f32 %0, %1;" : "=r"(a) : "f"(v.x));
        asm("cvt.rna.tf32.f32 %0, %1;" : "=r"(b) : "f"(v.y));
        asm("cvt.rna.tf32.f32 %0, %1;" : "=r"(c) : "f"(v.z));
        asm("cvt.rna.tf32.f32 %0, %1;" : "=r"(d) : "f"(v.w));
        float4 o = make_float4(__uint_as_float(a), __uint_as_float(b),
                               __uint_as_float(c), __uint_as_float(d));
        *reinterpret_cast<float4*>(g_w_tf32 + i) = o;
    }
}

// ---------------- main GEMM ----------------
__global__ __launch_bounds__(THREADS, 2)
void scl_tf32_v4(const float* __restrict__ x,
                 const int*   __restrict__ sid,
                 const float* __restrict__ bias,
                 float*       __restrict__ y) {
    extern __shared__ float smf[];
    float* As = smf;                    // [STAGES][ATILE]
    float* Bs = smf + STAGES * ATILE;   // [STAGES][ATILE]

    const int b  = blockIdx.z;
    const int s  = __ldg(&sid[b]);
    const int m0 = blockIdx.y * BM;     // N (query) tile
    const int n0 = blockIdx.x * BN;     // O tile

    const float* xb = x        + (size_t)b * NQ * HD + (size_t)m0 * HD;
    const float* wb = g_w_tf32 + (size_t)s * OD * HD + (size_t)n0 * HD;

    const int tid  = threadIdx.x;
    const int lrow = tid >> 2;          // 0..31 loader row base
    const int lq   = (tid & 3) * 4;     // 0,4,8,12 loader col

    const int wid  = tid >> 5;          // 0..3
    const int lane = tid & 31;
    const int g    = lane >> 2;         // groupID 0..7
    const int tg   = lane & 3;          // threadInGroup 0..3
    const int wm   = (wid & 1) * 64;    // warp M offset
    const int wn   = (wid >> 1) * 64;   // warp N offset

    float acc[4][8][4];
    #pragma unroll
    for (int i = 0; i < 4; i++)
        #pragma unroll
        for (int j = 0; j < 8; j++)
            #pragma unroll
            for (int k = 0; k < 4; k++) acc[i][j][k] = 0.f;

    // Double-buffered register fragments
    uint32_t afA[4][4], bfA[8][2];   // holds ks=0 frags of current tile
    uint32_t afB[4][4], bfB[8][2];   // holds ks=1 frags of current tile

    auto load_stage = [&](int st, int k0) {
        float* Ad = As + st * ATILE;
        float* Bd = Bs + st * ATILE;
        #pragma unroll
        for (int i = 0; i < 4; i++) {
            const int row = lrow + i * 32;
            cp_async16(cvta_smem(Ad + row * LDA + lq), xb + (size_t)row * HD + k0 + lq);
            cp_async16(cvta_smem(Bd + row * LDA + lq), wb + (size_t)row * HD + k0 + lq);
        }
    };

    auto ldfrag = [&](uint32_t af[4][4], uint32_t bf[8][2],
                      const float* A, const float* Bsm, int kl) {
        #pragma unroll
        for (int mi = 0; mi < 4; mi++) {
            const int r0 = wm + mi * 16 + g;
            af[mi][0] = __float_as_uint(A[ r0      * LDA + kl + tg    ]);
            af[mi][1] = __float_as_uint(A[(r0 + 8) * LDA + kl + tg    ]);
            af[mi][2] = __float_as_uint(A[ r0      * LDA + kl + tg + 4]);
            af[mi][3] = __float_as_uint(A[(r0 + 8) * LDA + kl + tg + 4]);
        }
        #pragma unroll
        for (int ni = 0; ni < 8; ni++) {
            const int c0 = wn + ni * 8 + g;
            bf[ni][0] = __float_as_uint(Bsm[c0 * LDA + kl + tg    ]);
            bf[ni][1] = __float_as_uint(Bsm[c0 * LDA + kl + tg + 4]);
        }
    };

    auto domma = [&](uint32_t af[4][4], uint32_t bf[8][2]) {
        #pragma unroll
        for (int mi = 0; mi < 4; mi++)
            #pragma unroll
            for (int ni = 0; ni < 8; ni++) {
                asm volatile(
                    "mma.sync.aligned.m16n8k8.row.col.f32.tf32.tf32.f32 "
                    "{%0,%1,%2,%3}, {%4,%5,%6,%7}, {%8,%9}, {%0,%1,%2,%3};\n"
                    : "+f"(acc[mi][ni][0]), "+f"(acc[mi][ni][1]),
                      "+f"(acc[mi][ni][2]), "+f"(acc[mi][ni][3])
                    : "r"(af[mi][0]), "r"(af[mi][1]),
                      "r"(af[mi][2]), "r"(af[mi][3]),
                      "r"(bf[ni][0]), "r"(bf[ni][1]));
            }
    };

    // Prologue: fill STAGES-1 stages
    #pragma unroll
    for (int p = 0; p < STAGES - 1; p++) {
        load_stage(p, p * BK);
        asm volatile("cp.async.commit_group;\n" ::: "memory");
    }
    asm volatile("cp.async.wait_group %0;\n" :: "n"(STAGES - 2) : "memory");
    __syncthreads();
    ldfrag(afA, bfA, As, Bs, 0);   // tile 0, ks=0

    for (int kt = 0; kt < KTILES; kt++) {
        const int cs = kt & (STAGES - 1);
        const float* A   = As + cs * ATILE;
        const float* Bsm = Bs + cs * ATILE;

        // Issue TMA-ish loads for tile kt+3 (slot == (kt-1)&3, safe: all warps
        // passed iteration kt-1's mid-barrier, which orders all reads of it)
        const int nx = kt + STAGES - 1;
        if (nx < KTILES) load_stage(nx & (STAGES - 1), nx * BK);
        asm volatile("cp.async.commit_group;\n" ::: "memory");

        // ks=0 HMMAs overlap ks=1 fragment loads
        ldfrag(afB, bfB, A, Bsm, 8);
        domma(afA, bfA);

        // Guarantee tile kt+1 complete (this thread) + cross-thread visible
        asm volatile("cp.async.wait_group %0;\n" :: "n"(STAGES - 2) : "memory");
        __syncthreads();

        // ks=1 HMMAs overlap next tile's ks=0 fragment loads
        if (kt + 1 < KTILES) {
            const int ns = (kt + 1) & (STAGES - 1);
            ldfrag(afA, bfA, As + ns * ATILE, Bs + ns * ATILE, 0);
        }
        domma(afB, bfB);
    }

    // Epilogue: bias add + store
    const float* bb = bias + (size_t)s * OD + n0;
    float* yb = y + (size_t)b * NQ * OD + (size_t)m0 * OD + n0;

    #pragma unroll
    for (int mi = 0; mi < 4; mi++) {
        const int row = wm + mi * 16 + g;
        #pragma unroll
        for (int ni = 0; ni < 8; ni++) {
            const int col = wn + ni * 8 + tg * 2;
            const float b0v = __ldg(&bb[col]);
            const float b1v = __ldg(&bb[col + 1]);
            float2 v0 = make_float2(acc[mi][ni][0] + b0v, acc[mi][ni][1] + b1v);
            float2 v1 = make_float2(acc[mi][ni][2] + b0v, acc[mi][ni][3] + b1v);
            *reinterpret_cast<float2*>(&yb[(size_t)row * OD + col])       = v0;
            *reinterpret_cast<float2*>(&yb[(size_t)(row + 8) * OD + col]) = v1;
        }
    }
}

extern "C" void kernel_launch(void* const* d_in, const int* in_sizes, int n_in,
                              void* d_out, int out_size) {
    const float* x    = (const float*)d_in[0];
    const int*   sid  = (const int*)  d_in[1];
    const float* w    = (const float*)d_in[2];
    const float* bias = (const float*)d_in[3];
    float* y = (float*)d_out;

    round_w_kernel<<<1024, 256>>>(w);

    cudaFuncSetAttribute(scl_tf32_v4, cudaFuncAttributeMaxDynamicSharedMemorySize, SMEM_BYTES);

    dim3 grid(OD / BN, NQ / BM, BATCH);  // (8, 4, 32)
    scl_tf32_v4<<<grid, THREADS, SMEM_BYTES>>>(x, sid, bias, y);
}

// round 7
// speedup vs baseline: 1.6505x; 1.2525x over previous
#include <cuda_runtime.h>
#include <cuda.h>
#include <cstdint>

// Problem constants
#define BATCH 32
#define NQ    512
#define HD    1024
#define OD    1024
#define NSUBJ 8

// Tiling: CTA 128x128, 4 warps each computing 64x64; K chunk = 32 floats (128B SW128 rows)
#define BM 128
#define BN 128
#define BKF 32
#define CHUNKS (HD / BKF)    // 32
#define NST 3                // pipeline stages
#define THREADS 128

// SMEM layout
#define SMB_FULL(s)  ((s) * 8)          // 3 full barriers
#define SMB_EMPTY(s) (24 + (s) * 8)     // 3 empty barriers
#define SM_A(s)      (1024 + (s) * 32768)
#define SM_B(s)      (SM_A(s) + 16384)
#define STAGE_BYTES  32768
#define SMEM_TOTAL   (1024 + NST * STAGE_BYTES)   // 99328

// Scratch: weight pre-rounded to nearest-tf32 (MMA truncates raw fp32 operands)
__device__ float g_w_tf32[(size_t)NSUBJ * OD * HD];

__device__ __forceinline__ uint32_t smem_u32(const void* p) {
    return (uint32_t)__cvta_generic_to_shared(p);
}
__device__ __forceinline__ void mbar_init(uint32_t a, uint32_t cnt) {
    asm volatile("mbarrier.init.shared.b64 [%0], %1;" :: "r"(a), "r"(cnt) : "memory");
}
__device__ __forceinline__ void mbar_expect_tx(uint32_t a, uint32_t bytes) {
    asm volatile("mbarrier.arrive.expect_tx.shared.b64 _, [%0], %1;"
                 :: "r"(a), "r"(bytes) : "memory");
}
__device__ __forceinline__ void mbar_arrive(uint32_t a) {
    asm volatile("mbarrier.arrive.shared.b64 _, [%0];" :: "r"(a) : "memory");
}
__device__ __forceinline__ void mbar_wait(uint32_t a, uint32_t parity) {
    asm volatile(
        "{\n\t.reg .pred P;\n"
        "WL%=:\n\tmbarrier.try_wait.parity.shared.b64 P, [%0], %1;\n"
        "\t@P bra WD%=;\n\tbra WL%=;\nWD%=:\n\t}"
        :: "r"(a), "r"(parity) : "memory");
}
__device__ __forceinline__ void tma_load_3d(uint32_t dst, const CUtensorMap* tm,
                                            int cx, int cy, int cz, uint32_t mbar) {
    asm volatile(
        "cp.async.bulk.tensor.3d.shared::cta.global.tile.mbarrier::complete_tx::bytes "
        "[%0], [%1, {%2, %3, %4}], [%5];"
        :: "r"(dst), "l"(tm), "r"(cx), "r"(cy), "r"(cz), "r"(mbar) : "memory");
}

// ---------------- prologue: round W to nearest-tf32 ----------------
__global__ void __launch_bounds__(256) round_w_kernel(const float* __restrict__ w) {
    const size_t n = (size_t)NSUBJ * OD * HD;
    size_t i = ((size_t)blockIdx.x * blockDim.x + threadIdx.x) * 4;
    const size_t stride = (size_t)gridDim.x * blockDim.x * 4;
    for (; i < n; i += stride) {
        float4 v = *reinterpret_cast<const float4*>(w + i);
        uint32_t a, b, c, d;
        asm("cvt.rna.tf32.f32 %0, %1;" : "=r"(a) : "f"(v.x));
        asm("cvt.rna.tf32.f32 %0, %1;" : "=r"(b) : "f"(v.y));
        asm("cvt.rna.tf32.f32 %0, %1;" : "=r"(c) : "f"(v.z));
        asm("cvt.rna.tf32.f32 %0, %1;" : "=r"(d) : "f"(v.w));
        float4 o = make_float4(__uint_as_float(a), __uint_as_float(b),
                               __uint_as_float(c), __uint_as_float(d));
        *reinterpret_cast<float4*>(g_w_tf32 + i) = o;
    }
}

// ---------------- main GEMM ----------------
__global__ __launch_bounds__(THREADS, 2)
void scl_tf32_v5(const __grid_constant__ CUtensorMap tma_x,
                 const __grid_constant__ CUtensorMap tma_w,
                 const int*   __restrict__ sid,
                 const float* __restrict__ bias,
                 float*       __restrict__ y) {
    extern __shared__ char smem[];
    const uint32_t sb = smem_u32(smem);

    const int b  = blockIdx.z;
    const int s  = __ldg(&sid[b]);
    const int m0 = blockIdx.y * BM;     // N (query) tile
    const int n0 = blockIdx.x * BN;     // O tile

    const int tid  = threadIdx.x;
    const int wid  = tid >> 5;
    const int lane = tid & 31;
    const int g    = lane >> 2;         // groupID 0..7
    const int tg   = lane & 3;          // threadInGroup 0..3
    const int gx   = g << 2;            // SW128 XOR term (word units)
    const int wm   = (wid & 1) * 64;    // warp M offset
    const int wn   = (wid >> 1) * 64;   // warp N offset

    // Barrier init + initial TMA issues
    if (tid == 0) {
        for (int st = 0; st < NST; st++) {
            mbar_init(sb + SMB_FULL(st), 1);
            mbar_init(sb + SMB_EMPTY(st), 4);
        }
    }
    __syncthreads();
    if (tid == 0) {
        for (int c = 0; c < NST; c++) {
            mbar_expect_tx(sb + SMB_FULL(c), STAGE_BYTES);
            tma_load_3d(sb + SM_A(c), &tma_x, c * BKF, m0, b, sb + SMB_FULL(c));
            tma_load_3d(sb + SM_B(c), &tma_w, c * BKF, n0, s, sb + SMB_FULL(c));
        }
    }

    float acc[4][8][4];
    #pragma unroll
    for (int i = 0; i < 4; i++)
        #pragma unroll
        for (int j = 0; j < 8; j++)
            #pragma unroll
            for (int k = 0; k < 4; k++) acc[i][j][k] = 0.f;

    uint32_t af0[4][4], bf0[8][2];   // frag buffer 0
    uint32_t af1[4][4], bf1[8][2];   // frag buffer 1

    // Fragment load from an SW128-swizzled 128x(32 float) tile.
    // word index within row = k ^ (row&7)<<2 ; rows r0, r0+8 share (row&7)=g.
    auto ldfrag = [&](uint32_t af[4][4], uint32_t bf[8][2],
                      const float* A, const float* Bsm, int kl) {
        const int c0k = (kl + tg) ^ gx;
        const int c1k = (kl + tg + 4) ^ gx;
        #pragma unroll
        for (int mi = 0; mi < 4; mi++) {
            const int r0 = wm + mi * 16 + g;
            af[mi][0] = __float_as_uint(A[ r0      * 32 + c0k]);
            af[mi][1] = __float_as_uint(A[(r0 + 8) * 32 + c0k]);
            af[mi][2] = __float_as_uint(A[ r0      * 32 + c1k]);
            af[mi][3] = __float_as_uint(A[(r0 + 8) * 32 + c1k]);
        }
        #pragma unroll
        for (int ni = 0; ni < 8; ni++) {
            const int c0 = wn + ni * 8 + g;
            bf[ni][0] = __float_as_uint(Bsm[c0 * 32 + c0k]);
            bf[ni][1] = __float_as_uint(Bsm[c0 * 32 + c1k]);
        }
    };

    auto domma = [&](uint32_t af[4][4], uint32_t bf[8][2]) {
        #pragma unroll
        for (int mi = 0; mi < 4; mi++)
            #pragma unroll
            for (int ni = 0; ni < 8; ni++) {
                asm volatile(
                    "mma.sync.aligned.m16n8k8.row.col.f32.tf32.tf32.f32 "
                    "{%0,%1,%2,%3}, {%4,%5,%6,%7}, {%8,%9}, {%0,%1,%2,%3};\n"
                    : "+f"(acc[mi][ni][0]), "+f"(acc[mi][ni][1]),
                      "+f"(acc[mi][ni][2]), "+f"(acc[mi][ni][3])
                    : "r"(af[mi][0]), "r"(af[mi][1]),
                      "r"(af[mi][2]), "r"(af[mi][3]),
                      "r"(bf[ni][0]), "r"(bf[ni][1]));
            }
    };

    // Wait chunk 0, preload its ks=0 fragments
    int ws = 0, wp = 0;                 // full-wait cursor
    mbar_wait(sb + SMB_FULL(0), 0);
    if (++ws == NST) { ws = 0; wp ^= 1; }
    ldfrag(af0, bf0, (const float*)(smem + SM_A(0)), (const float*)(smem + SM_B(0)), 0);

    for (int kt = 0; kt < CHUNKS; kt++) {
        const int st = kt % NST;
        const float* A   = (const float*)(smem + SM_A(st));
        const float* Bsm = (const float*)(smem + SM_B(st));

        ldfrag(af1, bf1, A, Bsm, 8);
        domma(af0, bf0);
        ldfrag(af0, bf0, A, Bsm, 16);
        domma(af1, bf1);
        ldfrag(af1, bf1, A, Bsm, 24);
        domma(af0, bf0);

        if (kt + 1 < CHUNKS) {
            const int ns = (kt + 1) % NST;
            mbar_wait(sb + SMB_FULL(ns), (uint32_t)wp);
            if (++ws == NST) { ws = 0; wp ^= 1; }
            ldfrag(af0, bf0, (const float*)(smem + SM_A(ns)),
                             (const float*)(smem + SM_B(ns)), 0);
        }
        domma(af1, bf1);

        // Signal this stage consumed (frag values already consumed by issued MMAs)
        if (lane == 0) mbar_arrive(sb + SMB_EMPTY(st));

        // Producer: refill this slot with chunk kt+3 once all 4 warps arrived
        if (tid == 0 && kt + NST < CHUNKS) {
            mbar_wait(sb + SMB_EMPTY(st), (uint32_t)((kt / NST) & 1));
            mbar_expect_tx(sb + SMB_FULL(st), STAGE_BYTES);
            const int c = kt + NST;
            tma_load_3d(sb + SM_A(st), &tma_x, c * BKF, m0, b, sb + SMB_FULL(st));
            tma_load_3d(sb + SM_B(st), &tma_w, c * BKF, n0, s, sb + SMB_FULL(st));
        }
    }

    // Epilogue: bias add + store
    const float* bb = bias + (size_t)s * OD + n0;
    float* yb = y + (size_t)b * NQ * OD + (size_t)m0 * OD + n0;

    #pragma unroll
    for (int mi = 0; mi < 4; mi++) {
        const int row = wm + mi * 16 + g;
        #pragma unroll
        for (int ni = 0; ni < 8; ni++) {
            const int col = wn + ni * 8 + tg * 2;
            const float b0v = __ldg(&bb[col]);
            const float b1v = __ldg(&bb[col + 1]);
            float2 v0 = make_float2(acc[mi][ni][0] + b0v, acc[mi][ni][1] + b1v);
            float2 v1 = make_float2(acc[mi][ni][2] + b0v, acc[mi][ni][3] + b1v);
            *reinterpret_cast<float2*>(&yb[(size_t)row * OD + col])       = v0;
            *reinterpret_cast<float2*>(&yb[(size_t)(row + 8) * OD + col]) = v1;
        }
    }
}

// ---------------- host launch ----------------
typedef int (*PFN_encodeTiled)(
    CUtensorMap*, int, unsigned int, void*,
    const unsigned long long*, const unsigned long long*,
    const unsigned int*, const unsigned int*,
    int, int, int, int);

extern "C" void kernel_launch(void* const* d_in, const int* in_sizes, int n_in,
                              void* d_out, int out_size) {
    const float* x    = (const float*)d_in[0];
    const int*   sid  = (const int*)  d_in[1];
    const float* w    = (const float*)d_in[2];
    const float* bias = (const float*)d_in[3];
    float* y = (float*)d_out;

    round_w_kernel<<<1024, 256>>>(w);

    void* wscratch = nullptr;
    cudaGetSymbolAddress(&wscratch, g_w_tf32);

    PFN_encodeTiled enc = nullptr;
    cudaDriverEntryPointQueryResult qr;
    cudaGetDriverEntryPoint("cuTensorMapEncodeTiled", (void**)&enc, cudaEnableDefault, &qr);

    // Enum ABI values: FLOAT32=7, interleave NONE=0, SWIZZLE_128B=3, L2_128B=2, OOB NONE=0
    CUtensorMap tx{}, tw{};
    {
        unsigned long long dims[3]    = {HD, NQ, BATCH};
        unsigned long long strides[2] = {HD * 4ull, (unsigned long long)NQ * HD * 4ull};
        unsigned int box[3]           = {BKF, BM, 1};
        unsigned int es[3]            = {1, 1, 1};
        enc(&tx, 7, 3, (void*)x, dims, strides, box, es, 0, 3, 2, 0);
    }
    {
        unsigned long long dims[3]    = {HD, OD, NSUBJ};
        unsigned long long strides[2] = {HD * 4ull, (unsigned long long)OD * HD * 4ull};
        unsigned int box[3]           = {BKF, BN, 1};
        unsigned int es[3]            = {1, 1, 1};
        enc(&tw, 7, 3, wscratch, dims, strides, box, es, 0, 3, 2, 0);
    }

    cudaFuncSetAttribute(scl_tf32_v5, cudaFuncAttributeMaxDynamicSharedMemorySize, SMEM_TOTAL);

    dim3 grid(OD / BN, NQ / BM, BATCH);  // (8, 4, 32)
    scl_tf32_v5<<<grid, THREADS, SMEM_TOTAL>>>(tx, tw, sid, bias, y);
}

// round 8
// speedup vs baseline: 1.6518x; 1.0008x over previous
#include <cuda_runtime.h>
#include <cuda.h>
#include <cstdint>

// Problem constants
#define BATCH 32
#define NQ    512
#define HD    1024
#define OD    1024
#define NSUBJ 8

// Tiling: CTA 128x128, 4 warps each computing 64x64; K chunk = 32 floats (128B SW128 rows)
#define BM 128
#define BN 128
#define BKF 32
#define CHUNKS (HD / BKF)    // 32
#define NST 3                // pipeline stages
#define THREADS 128

// SMEM layout
#define SMB_FULL(s)  ((s) * 8)          // 3 full barriers
#define SMB_EMPTY(s) (24 + (s) * 8)     // 3 empty barriers
#define SM_A(s)      (1024 + (s) * 32768)
#define SM_B(s)      (SM_A(s) + 16384)
#define STAGE_BYTES  32768
#define SMEM_TOTAL   (1024 + NST * STAGE_BYTES)   // 99328

__device__ __forceinline__ uint32_t smem_u32(const void* p) {
    return (uint32_t)__cvta_generic_to_shared(p);
}
__device__ __forceinline__ void mbar_init(uint32_t a, uint32_t cnt) {
    asm volatile("mbarrier.init.shared.b64 [%0], %1;" :: "r"(a), "r"(cnt) : "memory");
}
__device__ __forceinline__ void mbar_expect_tx(uint32_t a, uint32_t bytes) {
    asm volatile("mbarrier.arrive.expect_tx.shared.b64 _, [%0], %1;"
                 :: "r"(a), "r"(bytes) : "memory");
}
__device__ __forceinline__ void mbar_arrive(uint32_t a) {
    asm volatile("mbarrier.arrive.shared.b64 _, [%0];" :: "r"(a) : "memory");
}
__device__ __forceinline__ void mbar_wait(uint32_t a, uint32_t parity) {
    asm volatile(
        "{\n\t.reg .pred P;\n"
        "WL%=:\n\tmbarrier.try_wait.parity.shared.b64 P, [%0], %1;\n"
        "\t@P bra WD%=;\n\tbra WL%=;\nWD%=:\n\t}"
        :: "r"(a), "r"(parity) : "memory");
}
__device__ __forceinline__ void tma_load_3d(uint32_t dst, const CUtensorMap* tm,
                                            int cx, int cy, int cz, uint32_t mbar) {
    asm volatile(
        "cp.async.bulk.tensor.3d.shared::cta.global.tile.mbarrier::complete_tx::bytes "
        "[%0], [%1, {%2, %3, %4}], [%5];"
        :: "r"(dst), "l"(tm), "r"(cx), "r"(cy), "r"(cz), "r"(mbar) : "memory");
}
__device__ __forceinline__ uint32_t f2tf32(float f) {
    uint32_t r;
    asm("cvt.rna.tf32.f32 %0, %1;\n" : "=r"(r) : "f"(f));
    return r;
}

// ---------------- main GEMM ----------------
__global__ __launch_bounds__(THREADS, 2)
void scl_tf32_v6(const __grid_constant__ CUtensorMap tma_x,
                 const __grid_constant__ CUtensorMap tma_w,
                 const int*   __restrict__ sid,
                 const float* __restrict__ bias,
                 float*       __restrict__ y) {
    extern __shared__ char smem[];
    const uint32_t sb = smem_u32(smem);

    const int b  = blockIdx.z;
    const int s  = __ldg(&sid[b]);
    const int m0 = blockIdx.y * BM;     // N (query) tile
    const int n0 = blockIdx.x * BN;     // O tile

    const int tid  = threadIdx.x;
    const int wid  = tid >> 5;
    const int lane = tid & 31;
    const int g    = lane >> 2;         // groupID 0..7
    const int tg   = lane & 3;          // threadInGroup 0..3
    const int gx   = g << 2;            // SW128 XOR term (word units)
    const int wm   = (wid & 1) * 64;    // warp M offset
    const int wn   = (wid >> 1) * 64;   // warp N offset

    // Barrier init + initial TMA issues
    if (tid == 0) {
        for (int st = 0; st < NST; st++) {
            mbar_init(sb + SMB_FULL(st), 1);
            mbar_init(sb + SMB_EMPTY(st), 4);
        }
    }
    __syncthreads();
    if (tid == 0) {
        for (int c = 0; c < NST; c++) {
            mbar_expect_tx(sb + SMB_FULL(c), STAGE_BYTES);
            tma_load_3d(sb + SM_A(c), &tma_x, c * BKF, m0, b, sb + SMB_FULL(c));
            tma_load_3d(sb + SM_B(c), &tma_w, c * BKF, n0, s, sb + SMB_FULL(c));
        }
    }

    float acc[4][8][4];
    #pragma unroll
    for (int i = 0; i < 4; i++)
        #pragma unroll
        for (int j = 0; j < 8; j++)
            #pragma unroll
            for (int k = 0; k < 4; k++) acc[i][j][k] = 0.f;

    uint32_t af0[4][4], bf0[8][2];   // frag buffer 0
    uint32_t af1[4][4], bf1[8][2];   // frag buffer 1

    // Fragment load from an SW128-swizzled 128x(32 float) tile.
    // A (x): fed raw — HW truncates fp32->tf32 (as in all prior rounds).
    // B (W): RNA-rounded here via cvt.rna.tf32 — numerically identical to
    //        the old pre-rounding prologue, without the 64MB pass.
    auto ldfrag = [&](uint32_t af[4][4], uint32_t bf[8][2],
                      const float* A, const float* Bsm, int kl) {
        const int c0k = (kl + tg) ^ gx;
        const int c1k = (kl + tg + 4) ^ gx;
        #pragma unroll
        for (int mi = 0; mi < 4; mi++) {
            const int r0 = wm + mi * 16 + g;
            af[mi][0] = __float_as_uint(A[ r0      * 32 + c0k]);
            af[mi][1] = __float_as_uint(A[(r0 + 8) * 32 + c0k]);
            af[mi][2] = __float_as_uint(A[ r0      * 32 + c1k]);
            af[mi][3] = __float_as_uint(A[(r0 + 8) * 32 + c1k]);
        }
        #pragma unroll
        for (int ni = 0; ni < 8; ni++) {
            const int c0 = wn + ni * 8 + g;
            bf[ni][0] = f2tf32(Bsm[c0 * 32 + c0k]);
            bf[ni][1] = f2tf32(Bsm[c0 * 32 + c1k]);
        }
    };

    auto domma = [&](uint32_t af[4][4], uint32_t bf[8][2]) {
        #pragma unroll
        for (int mi = 0; mi < 4; mi++)
            #pragma unroll
            for (int ni = 0; ni < 8; ni++) {
                asm volatile(
                    "mma.sync.aligned.m16n8k8.row.col.f32.tf32.tf32.f32 "
                    "{%0,%1,%2,%3}, {%4,%5,%6,%7}, {%8,%9}, {%0,%1,%2,%3};\n"
                    : "+f"(acc[mi][ni][0]), "+f"(acc[mi][ni][1]),
                      "+f"(acc[mi][ni][2]), "+f"(acc[mi][ni][3])
                    : "r"(af[mi][0]), "r"(af[mi][1]),
                      "r"(af[mi][2]), "r"(af[mi][3]),
                      "r"(bf[ni][0]), "r"(bf[ni][1]));
            }
    };

    // Wait chunk 0, preload its ks=0 fragments
    mbar_wait(sb + SMB_FULL(0), 0);
    ldfrag(af0, bf0, (const float*)(smem + SM_A(0)), (const float*)(smem + SM_B(0)), 0);

    int wp = 0;   // parity of the NEXT full-wait (stage cursor tracked via kt)
    for (int kt = 0; kt < CHUNKS; kt++) {
        const int st = kt % NST;
        const float* A   = (const float*)(smem + SM_A(st));
        const float* Bsm = (const float*)(smem + SM_B(st));

        ldfrag(af1, bf1, A, Bsm, 8);
        domma(af0, bf0);
        ldfrag(af0, bf0, A, Bsm, 16);
        domma(af1, bf1);
        ldfrag(af1, bf1, A, Bsm, 24);
        domma(af0, bf0);

        if (kt + 1 < CHUNKS) {
            const int ns = (kt + 1) % NST;
            if (ns == 0) wp ^= 1;
            mbar_wait(sb + SMB_FULL(ns), (uint32_t)wp);
            ldfrag(af0, bf0, (const float*)(smem + SM_A(ns)),
                             (const float*)(smem + SM_B(ns)), 0);
        }
        domma(af1, bf1);

        // Signal this stage consumed
        if (lane == 0) mbar_arrive(sb + SMB_EMPTY(st));

        // Producer: refill this slot with chunk kt+NST once all 4 warps arrived
        if (tid == 0 && kt + NST < CHUNKS) {
            mbar_wait(sb + SMB_EMPTY(st), (uint32_t)((kt / NST) & 1));
            mbar_expect_tx(sb + SMB_FULL(st), STAGE_BYTES);
            const int c = kt + NST;
            tma_load_3d(sb + SM_A(st), &tma_x, c * BKF, m0, b, sb + SMB_FULL(st));
            tma_load_3d(sb + SM_B(st), &tma_w, c * BKF, n0, s, sb + SMB_FULL(st));
        }
    }

    // Epilogue: bias add + store
    const float* bb = bias + (size_t)s * OD + n0;
    float* yb = y + (size_t)b * NQ * OD + (size_t)m0 * OD + n0;

    #pragma unroll
    for (int mi = 0; mi < 4; mi++) {
        const int row = wm + mi * 16 + g;
        #pragma unroll
        for (int ni = 0; ni < 8; ni++) {
            const int col = wn + ni * 8 + tg * 2;
            const float b0v = __ldg(&bb[col]);
            const float b1v = __ldg(&bb[col + 1]);
            float2 v0 = make_float2(acc[mi][ni][0] + b0v, acc[mi][ni][1] + b1v);
            float2 v1 = make_float2(acc[mi][ni][2] + b0v, acc[mi][ni][3] + b1v);
            *reinterpret_cast<float2*>(&yb[(size_t)row * OD + col])       = v0;
            *reinterpret_cast<float2*>(&yb[(size_t)(row + 8) * OD + col]) = v1;
        }
    }
}

// ---------------- host launch ----------------
typedef int (*PFN_encodeTiled)(
    CUtensorMap*, int, unsigned int, void*,
    const unsigned long long*, const unsigned long long*,
    const unsigned int*, const unsigned int*,
    int, int, int, int);

extern "C" void kernel_launch(void* const* d_in, const int* in_sizes, int n_in,
                              void* d_out, int out_size) {
    const float* x    = (const float*)d_in[0];
    const int*   sid  = (const int*)  d_in[1];
    const float* w    = (const float*)d_in[2];
    const float* bias = (const float*)d_in[3];
    float* y = (float*)d_out;

    PFN_encodeTiled enc = nullptr;
    cudaDriverEntryPointQueryResult qr;
    cudaGetDriverEntryPoint("cuTensorMapEncodeTiled", (void**)&enc, cudaEnableDefault, &qr);

    // Enum ABI values: FLOAT32=7, interleave NONE=0, SWIZZLE_128B=3, L2_128B=2, OOB NONE=0
    CUtensorMap tx{}, tw{};
    {
        unsigned long long dims[3]    = {HD, NQ, BATCH};
        unsigned long long strides[2] = {HD * 4ull, (unsigned long long)NQ * HD * 4ull};
        unsigned int box[3]           = {BKF, BM, 1};
        unsigned int es[3]            = {1, 1, 1};
        enc(&tx, 7, 3, (void*)x, dims, strides, box, es, 0, 3, 2, 0);
    }
    {
        unsigned long long dims[3]    = {HD, OD, NSUBJ};
        unsigned long long strides[2] = {HD * 4ull, (unsigned long long)OD * HD * 4ull};
        unsigned int box[3]           = {BKF, BN, 1};
        unsigned int es[3]            = {1, 1, 1};
        enc(&tw, 7, 3, (void*)w, dims, strides, box, es, 0, 3, 2, 0);
    }

    cudaFuncSetAttribute(scl_tf32_v6, cudaFuncAttributeMaxDynamicSharedMemorySize, SMEM_TOTAL);

    dim3 grid(OD / BN, NQ / BM, BATCH);  // (8, 4, 32)
    scl_tf32_v6<<<grid, THREADS, SMEM_TOTAL>>>(tx, tw, sid, bias, y);
}